// round 3
// baseline (speedup 1.0000x reference)
#include <cuda_runtime.h>

#define N_NODES 50000
#define E_EDGES 800000
#define IN_DIM  128
#define OUT_DIM 64
#define HEADS   4
#define HC      256      // HEADS*OUT_DIM
#define Q_HID   32
#define NEG_SLOPE 0.2f

// ---------------- scratch (static device memory; no allocations) ----------------
__device__ __align__(16) float g_h[N_NODES * HC];   // 51.2 MB  h = x@W
__device__ float g_asrc[N_NODES * HEADS];
__device__ float g_adst[N_NODES * HEADS];
__device__ __align__(16) float g_ex[E_EDGES * HEADS];
__device__ __align__(16) float g_den[N_NODES * HEADS];
__device__ float g_acc[N_NODES * OUT_DIM];
__device__ __align__(16) float g_v[64 * HEADS];     // W_edge contracted with att_edge
__device__ __align__(16) float g_wq2v[Q_HID * HEADS];
__device__ float g_bq2v[HEADS];
__device__ float g_t[OUT_DIM];
__device__ int   g_src[E_EDGES];
__device__ int   g_dst[E_EDGES];
__device__ int   g_idx_is64;

// ---------------- K_detect: is edge_index int64 or int32? -------------------
// If int64 (values < 2^31), every odd 32-bit word (high half) is 0.
// If int32, odd words are random node ids in [0,50000) — ~never 0.
__global__ void k_detect(const int* __restrict__ ei32) {
    if (threadIdx.x == 0) {
        int zeros = 0;
        for (int i = 1; i < 256; i += 2) zeros += (ei32[i] == 0);
        g_idx_is64 = (zeros > 64) ? 1 : 0;
    }
}

// ---------------- K_convert: expand edge_index to clean int32 ---------------
__global__ void k_convert(const void* __restrict__ ei) {
    int e = blockIdx.x * blockDim.x + threadIdx.x;
    if (e >= E_EDGES) return;
    if (g_idx_is64) {
        const long long* p = (const long long*)ei;
        g_src[e] = (int)p[e];
        g_dst[e] = (int)p[E_EDGES + e];
    } else {
        const int* p = (const int*)ei;
        g_src[e] = p[e];
        g_dst[e] = p[E_EDGES + e];
    }
}

// ---------------- K0: tiny precomputes (one block) ----------------
__global__ void k0_precompute(const float* __restrict__ W_edge,
                              const float* __restrict__ att_edge,
                              const float* __restrict__ Wq2,
                              const float* __restrict__ bq2,
                              const float* __restrict__ ns,
                              const float* __restrict__ Wc,
                              const float* __restrict__ bc) {
    int t = threadIdx.x; // 256 threads
    {   // v[d][hd] = sum_c W_edge[d, hd*64+c] * att_edge[hd, c]
        int d = t >> 2, hd = t & 3;
        float s = 0.f;
        #pragma unroll 8
        for (int c = 0; c < 64; ++c)
            s += W_edge[d * HC + hd * 64 + c] * att_edge[hd * 64 + c];
        g_v[t] = s;
    }
    __syncthreads();
    if (t < Q_HID * HEADS) {   // Wq2v[j][hd] = sum_d Wq2[j,d] * v[d][hd]
        int j = t >> 2, hd = t & 3;
        float s = 0.f;
        #pragma unroll 8
        for (int d = 0; d < 64; ++d)
            s += Wq2[j * 64 + d] * g_v[d * 4 + hd];
        g_wq2v[t] = s;
    }
    if (t >= 128 && t < 128 + HEADS) {
        int hd = t - 128;
        float s = 0.f;
        for (int d = 0; d < 64; ++d) s += bq2[d] * g_v[d * 4 + hd];
        g_bq2v[hd] = s;
    }
    if (t >= 192) {            // t[j] = bc[j] + sum_k ns[k]*Wc[64+k, j]
        int j = t - 192;
        float s = bc[j];
        #pragma unroll
        for (int k = 0; k < 8; ++k) s += ns[k] * Wc[(64 + k) * 64 + j];
        g_t[j] = s;
    }
}

// ---------------- K_init: zero den + acc ----------------
__global__ void k_init() {
    int i = blockIdx.x * blockDim.x + threadIdx.x;
    if (i < N_NODES * HEADS) g_den[i] = 0.f;
    if (i < N_NODES * OUT_DIM) g_acc[i] = 0.f;
}

// ---------------- K1: h = x @ W  (50000x128 @ 128x256) ----------------
__global__ void k1_gemm_h(const float* __restrict__ x, const float* __restrict__ W) {
    __shared__ float xs[IN_DIM * 16]; // transposed: xs[k*16 + m]
    int t = threadIdx.x;
    int n0 = blockIdx.x * 16;
    #pragma unroll
    for (int u = 0; u < 8; ++u) {
        int i = t + u * 256;
        int m = i >> 7, k = i & 127;
        xs[k * 16 + m] = x[(n0 + m) * IN_DIM + k];
    }
    __syncthreads();
    float acc[16];
    #pragma unroll
    for (int m = 0; m < 16; ++m) acc[m] = 0.f;
    #pragma unroll 4
    for (int k = 0; k < IN_DIM; ++k) {
        float w = W[k * HC + t];
        const float4* xp = (const float4*)(&xs[k * 16]);
        float4 a0 = xp[0], a1 = xp[1], a2 = xp[2], a3 = xp[3];
        acc[0]  += a0.x * w; acc[1]  += a0.y * w; acc[2]  += a0.z * w; acc[3]  += a0.w * w;
        acc[4]  += a1.x * w; acc[5]  += a1.y * w; acc[6]  += a1.z * w; acc[7]  += a1.w * w;
        acc[8]  += a2.x * w; acc[9]  += a2.y * w; acc[10] += a2.z * w; acc[11] += a2.w * w;
        acc[12] += a3.x * w; acc[13] += a3.y * w; acc[14] += a3.z * w; acc[15] += a3.w * w;
    }
    #pragma unroll
    for (int m = 0; m < 16; ++m)
        g_h[(n0 + m) * HC + t] = acc[m];
}

// ---------------- K1b: a_src/a_dst per node/head (warp per node) ----------------
__global__ void k1b_attn(const float* __restrict__ att_src,
                         const float* __restrict__ att_dst) {
    int warp = (blockIdx.x * blockDim.x + threadIdx.x) >> 5;
    int lane = threadIdx.x & 31;
    if (warp >= N_NODES) return;
    const float* hrow = &g_h[warp * HC];
    float s[HEADS], d[HEADS];
    #pragma unroll
    for (int hd = 0; hd < HEADS; ++hd) {
        float h1 = hrow[hd * 64 + lane], h2 = hrow[hd * 64 + 32 + lane];
        float as1 = att_src[hd * 64 + lane], as2 = att_src[hd * 64 + 32 + lane];
        float ad1 = att_dst[hd * 64 + lane], ad2 = att_dst[hd * 64 + 32 + lane];
        float ps = h1 * as1 + h2 * as2;
        float pd = h1 * ad1 + h2 * ad2;
        #pragma unroll
        for (int o = 16; o > 0; o >>= 1) {
            ps += __shfl_xor_sync(0xffffffffu, ps, o);
            pd += __shfl_xor_sync(0xffffffffu, pd, o);
        }
        s[hd] = ps; d[hd] = pd;
    }
    if (lane == 0) {
        #pragma unroll
        for (int hd = 0; hd < HEADS; ++hd) {
            g_asrc[warp * HEADS + hd] = s[hd];
            g_adst[warp * HEADS + hd] = d[hd];
        }
    }
}

// ---------------- K2: edge pass 1 — alpha, exp, denominator (warp per edge) ----
__global__ void k2_edge(const float* __restrict__ edge_attr,
                        const float* __restrict__ pq,
                        const float* __restrict__ Wq1,
                        const float* __restrict__ bq1) {
    int warp = (blockIdx.x * blockDim.x + threadIdx.x) >> 5;
    int lane = threadIdx.x & 31;
    if (warp >= E_EDGES) return;
    int e = warp;
    int src = g_src[e];
    int dst = g_dst[e];

    float p0 = 0.f, p1 = 0.f, p2 = 0.f, p3 = 0.f;
    const float* ea = &edge_attr[(long long)e * 64];
    #pragma unroll
    for (int r = 0; r < 2; ++r) {
        int dd = lane + r * 32;
        float a = ea[dd];
        float4 v = *(const float4*)&g_v[dd * 4];
        p0 += a * v.x; p1 += a * v.y; p2 += a * v.z; p3 += a * v.w;
    }
    // path-quality MLP, hidden unit j = lane (Q_HID == 32)
    float q0 = pq[e * 4 + 0] * 0.01f;
    float q1 = pq[e * 4 + 1] * 0.01f;
    float q2 = pq[e * 4 + 2] * 100.f;
    float q3 = pq[e * 4 + 3] * 100.f;
    float hj = q0 * Wq1[lane] + q1 * Wq1[32 + lane]
             + q2 * Wq1[64 + lane] + q3 * Wq1[96 + lane] + bq1[lane];
    hj = fmaxf(hj, 0.f);
    {
        float4 w = *(const float4*)&g_wq2v[lane * 4];
        p0 += hj * w.x; p1 += hj * w.y; p2 += hj * w.z; p3 += hj * w.w;
    }
    #pragma unroll
    for (int o = 16; o > 0; o >>= 1) {
        p0 += __shfl_xor_sync(0xffffffffu, p0, o);
        p1 += __shfl_xor_sync(0xffffffffu, p1, o);
        p2 += __shfl_xor_sync(0xffffffffu, p2, o);
        p3 += __shfl_xor_sync(0xffffffffu, p3, o);
    }
    // butterfly => every lane holds all 4 totals; lanes 0..3 each finish one head
    if (lane < 4) {
        float pe = (lane == 0) ? p0 : (lane == 1) ? p1 : (lane == 2) ? p2 : p3;
        float a = g_asrc[src * HEADS + lane] + g_adst[dst * HEADS + lane]
                + pe + g_bq2v[lane];
        a = (a > 0.f) ? a : NEG_SLOPE * a;   // leaky_relu
        float ex = expf(a);                  // max-shift omitted: exact same softmax
        g_ex[e * HEADS + lane] = ex;
        atomicAdd(&g_den[dst * HEADS + lane], ex);
    }
}

// ---------------- K4: edge pass 2 — weighted scatter (warp per edge) ----------
__global__ void k4_aggregate() {
    int warp = (blockIdx.x * blockDim.x + threadIdx.x) >> 5;
    int lane = threadIdx.x & 31;
    if (warp >= E_EDGES) return;
    int e = warp;
    int src = g_src[e];
    int dst = g_dst[e];

    float4 ex  = *(const float4*)&g_ex[e * 4];
    float4 den = *(const float4*)&g_den[dst * 4];
    float w0 = 0.25f * ex.x / den.x;
    float w1 = 0.25f * ex.y / den.y;
    float w2 = 0.25f * ex.z / den.z;
    float w3 = 0.25f * ex.w / den.w;

    int c = lane * 2;
    const float* hb = &g_h[src * HC];
    float2 h0 = *(const float2*)&hb[0 * 64 + c];
    float2 h1 = *(const float2*)&hb[1 * 64 + c];
    float2 h2 = *(const float2*)&hb[2 * 64 + c];
    float2 h3 = *(const float2*)&hb[3 * 64 + c];
    float mx = w0 * h0.x + w1 * h1.x + w2 * h2.x + w3 * h3.x;
    float my = w0 * h0.y + w1 * h1.y + w2 * h2.y + w3 * h3.y;
    atomicAdd(&g_acc[dst * OUT_DIM + c], mx);
    atomicAdd(&g_acc[dst * OUT_DIM + c + 1], my);
}

// ---------------- K5: out = relu(x_conv @ Wc[:64] + t)  (4 nodes/block) -------
__global__ void k5_out(const float* __restrict__ Wc,
                       const float* __restrict__ bias,
                       float* __restrict__ out) {
    __shared__ float xc[4][OUT_DIM];
    int t = threadIdx.x;
    int nl = t >> 6, j = t & 63;
    int n = blockIdx.x * 4 + nl;
    xc[nl][j] = g_acc[n * OUT_DIM + j] + bias[j];
    __syncthreads();
    float s = g_t[j];
    #pragma unroll 8
    for (int c = 0; c < OUT_DIM; ++c)
        s += xc[nl][c] * Wc[c * 64 + j];
    out[n * OUT_DIM + j] = fmaxf(s, 0.f);
}

// ---------------- launch ----------------
extern "C" void kernel_launch(void* const* d_in, const int* in_sizes, int n_in,
                              void* d_out, int out_size) {
    const float* x         = (const float*)d_in[0];
    const void*  ei        = d_in[1];                 // int32 or int64 — detected at runtime
    const float* edge_attr = (const float*)d_in[2];
    const float* pq        = (const float*)d_in[3];
    const float* ns        = (const float*)d_in[4];
    const float* W         = (const float*)d_in[5];
    const float* att_src   = (const float*)d_in[6];
    const float* att_dst   = (const float*)d_in[7];
    const float* W_edge    = (const float*)d_in[8];
    const float* att_edge  = (const float*)d_in[9];
    const float* bias      = (const float*)d_in[10];
    const float* Wq1       = (const float*)d_in[11];
    const float* bq1       = (const float*)d_in[12];
    const float* Wq2       = (const float*)d_in[13];
    const float* bq2       = (const float*)d_in[14];
    const float* Wc        = (const float*)d_in[15];
    const float* bc        = (const float*)d_in[16];
    float* out = (float*)d_out;

    k_detect<<<1, 32>>>((const int*)ei);
    k_convert<<<(E_EDGES + 255) / 256, 256>>>(ei);
    k0_precompute<<<1, 256>>>(W_edge, att_edge, Wq2, bq2, ns, Wc, bc);
    k_init<<<(N_NODES * OUT_DIM + 255) / 256, 256>>>();
    k1_gemm_h<<<N_NODES / 16, 256>>>(x, W);
    k1b_attn<<<(N_NODES * 32 + 255) / 256, 256>>>(att_src, att_dst);
    k2_edge<<<E_EDGES / 8, 256>>>(edge_attr, pq, Wq1, bq1);
    k4_aggregate<<<E_EDGES / 8, 256>>>();
    k5_out<<<N_NODES / 4, 256>>>(Wc, bias, out);
}